// round 7
// baseline (speedup 1.0000x reference)
#include <cuda_runtime.h>

#define BB 64
#define TT 4096
#define HH 128
#define GG 384   /* 3H */
#define NWORK 20 /* GEMM worker CTAs; 64+64+20 = 148 = full wave-1 residency */

// Scratch (allocation-free rule: __device__ globals)
__device__ float g_y0[(size_t)BB * TT * HH];    // layer-0 outputs [b][t][k]  128 MiB
__device__ float g_xg1[(size_t)BB * TT * GG];   // layer-1 ih gates [b][t][g] 402 MiB
__device__ float g_y1[(size_t)BB * TT * HH];    // layer-1 outputs [b][t][k]  128 MiB
__device__ int   g_flagA[BB * 32];              // y0 chunk ready  (producer -> worker)
__device__ int   g_flagB[BB * 32];              // xg1 chunk ready (worker -> consumer)

typedef unsigned long long ull;

static __device__ __forceinline__ ull pk(float a, float b) {
    ull r; asm("mov.b64 %0, {%1, %2};" : "=l"(r) : "f"(a), "f"(b)); return r;
}
static __device__ __forceinline__ void upk(ull v, float& a, float& b) {
    asm("mov.b64 {%0, %1}, %2;" : "=f"(a), "=f"(b) : "l"(v));
}
// Packed fp32x2 FMA / ADD (Blackwell): 2 ops per issue slot
static __device__ __forceinline__ void ffma2(ull& acc, ull a, ull b) {
    asm("fma.rn.f32x2 %0, %1, %2, %0;" : "+l"(acc) : "l"(a), "l"(b));
}
static __device__ __forceinline__ ull add2(ull a, ull b) {
    ull r; asm("add.rn.f32x2 %0, %1, %2;" : "=l"(r) : "l"(a), "l"(b)); return r;
}
static __device__ __forceinline__ float tanha(float x) {     // MUFU tanh
    float y; asm("tanh.approx.f32 %0, %1;" : "=f"(y) : "f"(x)); return y;
}
static __device__ __forceinline__ float sigfast(float x) {   // sigmoid via MUFU tanh
    return fmaf(0.5f, tanha(0.5f * x), 0.5f);
}
static __device__ __forceinline__ int ldacq(const int* p) {
    int v; asm volatile("ld.acquire.gpu.global.b32 %0, [%1];" : "=r"(v) : "l"(p) : "memory");
    return v;
}
static __device__ __forceinline__ void strel(int* p, int v) {
    asm volatile("st.release.gpu.global.b32 [%0], %1;" :: "l"(p), "r"(v) : "memory");
}
static __device__ __forceinline__ void stplain(int* p, int v) {
    asm volatile("st.global.b32 [%0], %1;" :: "l"(p), "r"(v) : "memory");
}

// Load one 128-float weight row into 64 packed register pairs.
static __device__ __forceinline__ void loadw(ull* w, const float* __restrict__ row) {
    const float4* r4 = (const float4*)row;
#pragma unroll
    for (int i = 0; i < 32; i++) {
        float4 v = r4[i];
        w[2 * i]     = pk(v.x, v.y);
        w[2 * i + 1] = pk(v.z, v.w);
    }
}

// dot(w_row[128], hsm[128]) with broadcast LDS.128 + packed FMA, 4 acc chains.
static __device__ __forceinline__ float dot128(const ull* w, const float* hsm) {
    const ulonglong2* h2 = (const ulonglong2*)hsm;
    ull a0 = 0, a1 = 0, a2 = 0, a3 = 0;
#pragma unroll
    for (int k = 0; k < 16; k++) {
        ulonglong2 p = h2[2 * k];
        ulonglong2 q = h2[2 * k + 1];
        ffma2(a0, w[4 * k + 0], p.x);
        ffma2(a1, w[4 * k + 1], p.y);
        ffma2(a2, w[4 * k + 2], q.x);
        ffma2(a3, w[4 * k + 3], q.y);
    }
    ull s = add2(add2(a0, a1), add2(a2, a3));
    float x0, x1; upk(s, x0, x1);
    return x0 + x1;
}

// ===== Wavefront mega-kernel (grid 148, all co-resident):
//   CTA 0..63    : layer-0 recurrence, batch b       (producer)
//   CTA 64..127  : layer-1 recurrence, batch b-64    (consumer, chunk-gated)
//   CTA 128..147 : xg1 GEMM workers (flagA -> chunk -> flagB)
// Dependency graph acyclic (consumer <- worker <- producer); producers never
// block => deadlock-free. Flags reset by their unique consumer => replay-safe.
// Recurrence layout: warp=tid>>5, grp=warp/3, role=warp%3 (0=r,1=z,2=n);
// group g owns units [32g,32g+32); named barrier (g+1) over its 96 threads;
// h double-buffered => one block barrier per step.
__global__ void __launch_bounds__(384, 1)
k_main(const float* __restrict__ data, const float* __restrict__ hidden,
       const float* __restrict__ w_ih0, const float* __restrict__ w_hh0,
       const float* __restrict__ b_ih0, const float* __restrict__ b_hh0,
       const float* __restrict__ w_ih1, const float* __restrict__ w_hh1,
       const float* __restrict__ b_ih1, const float* __restrict__ b_hh1,
       float* __restrict__ hT) {
    __shared__ __align__(16) float hsm[2][HH];
    __shared__ float s_z[HH];
    __shared__ __align__(8) float2 s_hx[HH];
    __shared__ __align__(16) float xbuf[512];
    __shared__ __align__(16) float ybuf[8 * HH];

    const int tid = threadIdx.x;

    if (blockIdx.x >= 2 * BB) {
        // ---------------- WORKER: xg1 = y0 @ w_ih1.T + b_ih1 ----------------
        const int wk = blockIdx.x - 2 * BB;
        ull w[64];
        loadw(w, w_ih1 + tid * HH);
        const float bi = b_ih1[tid];

        for (int task = wk; task < BB * 32; task += NWORK) {
            const int c = task >> 6, b = task & 63;   // chunk-major = production order
            if (tid == 0) {
                const int* f = g_flagA + b * 32 + c;
                while (ldacq(f) == 0) __nanosleep(64);
            }
            __syncthreads();
            const float* y0 = g_y0 + ((size_t)b * TT + (size_t)c * 128) * HH;
            float* xo = g_xg1 + ((size_t)b * TT + (size_t)c * 128) * GG;
            for (int tt = 0; tt < 128; tt += 8) {
                if (tid < 256) ((float4*)ybuf)[tid] = ((const float4*)(y0 + (size_t)tt * HH))[tid];
                __syncthreads();
#pragma unroll
                for (int r = 0; r < 8; r++) {
                    float acc = dot128(w, ybuf + r * HH);
                    xo[(size_t)(tt + r) * GG + tid] = acc + bi;
                }
                __syncthreads();
            }
            if (tid == 0) {
                stplain(g_flagA + b * 32 + c, 0);     // self-reset for next replay
                strel(g_flagB + b * 32 + c, 1);
            }
        }
        return;
    }

    const int warp = tid >> 5, lane = tid & 31;
    const int grp = warp / 3, role = warp - grp * 3;
    const int unit = (grp << 5) | lane;
    const int row = role * HH + unit;

    if (blockIdx.x < BB) {
        // ---------------- PRODUCER: layer-0 recurrence ----------------
        const int b = blockIdx.x;
        ull w[64];
        loadw(w, w_hh0 + row * HH);
        const float wi = w_ih0[row], bi = b_ih0[row], bh = b_hh0[row];

        float h_old = hidden[(size_t)b * HH + unit];
        if (role == 0) hsm[0][unit] = h_old;
        __syncthreads();

        const float* xg = data + (size_t)b * TT;
        float* y0 = g_y0 + (size_t)b * TT * HH;
        int* fl = g_flagA + b * 32;

        int cur = 0;
        for (int t = 0; t < TT; t++) {
            if ((t & 511) == 0) {
                if (tid < 128) ((float4*)xbuf)[tid] = ((const float4*)(xg + t))[tid];
                __syncthreads();
            }
            const float x = xbuf[t & 511];
            float acc = dot128(w, hsm[cur]) + bh;
            float xi = fmaf(x, wi, bi);
            float pre = acc + xi;
            float r_ = 0.f;
            if (role == 0) r_ = sigfast(pre);            // MUFU hidden under bar
            else if (role == 1) s_z[unit] = sigfast(pre); // z applied pre-bar
            else s_hx[unit] = make_float2(acc, xi);
            asm volatile("bar.sync %0, 96;" :: "r"(grp + 1) : "memory");
            if (role == 0) {
                float z = s_z[unit];
                float2 v = s_hx[unit];
                float n = tanha(fmaf(r_, v.x, v.y));
                h_old = fmaf(z, h_old - n, n);           // (1-z)n + z h
                hsm[cur ^ 1][unit] = h_old;
                y0[(size_t)t * HH + unit] = h_old;       // ship to workers
            }
            __syncthreads();
            // chunk-granular publish: barrier + release store => visible
            if (((t & 127) == 127) && tid == 0) strel(fl + (t >> 7), 1);
            cur ^= 1;
        }
        if (role == 0) hT[(size_t)b * HH + unit] = h_old;
    } else {
        // ---------------- CONSUMER: layer-1 recurrence ----------------
        const int b = blockIdx.x - BB;
        ull w[64];
        loadw(w, w_hh1 + row * HH);
        const float bh = b_hh1[row];

        float h_old = hidden[(size_t)BB * HH + (size_t)b * HH + unit];
        if (role == 0) hsm[0][unit] = h_old;   // ordered by first chunk's barrier

        const float* xgp = g_xg1 + (size_t)b * TT * GG + row;
        float* y1 = g_y1 + (size_t)b * TT * HH;
        int* fl = g_flagB + b * 32;

        int cur = 0;
        for (int c = 0; c < 32; c++) {
            if (tid == 0) {
                const int* f = fl + c;
                while (ldacq(f) == 0) __nanosleep(64);
            }
            __syncthreads();
            float xv = xgp[(size_t)(c * 128) * GG];
            for (int tt = 0; tt < 128; tt++) {
                const int t = c * 128 + tt;
                float acc = dot128(w, hsm[cur]) + bh;
                float xnext = (tt < 127) ? xgp[(size_t)(t + 1) * GG] : 0.f;  // prefetch
                float pre = acc + xv;
                float r_ = 0.f;
                if (role == 0) r_ = sigfast(pre);
                else if (role == 1) s_z[unit] = sigfast(pre);
                else s_hx[unit] = make_float2(acc, xv);
                asm volatile("bar.sync %0, 96;" :: "r"(grp + 1) : "memory");
                if (role == 0) {
                    float z = s_z[unit];
                    float2 v = s_hx[unit];
                    float n = tanha(fmaf(r_, v.x, v.y));
                    h_old = fmaf(z, h_old - n, n);
                    hsm[cur ^ 1][unit] = h_old;
                    y1[(size_t)t * HH + unit] = h_old;   // FC done by tail kernel
                }
                __syncthreads();
                xv = xnext;
                cur ^= 1;
            }
            if (tid == 0) stplain(fl + c, 0);            // self-reset
        }
        if (role == 0) hT[(size_t)BB * HH + (size_t)b * HH + unit] = h_old;
    }
}

// ---------- Tail: out[b,t] = relu(y1[b,t,:]) . fc_w + fc_b  (memory-bound) ----------
__global__ void __launch_bounds__(256)
k_fc(const float* __restrict__ fc_w, const float* __restrict__ fc_b,
     float* __restrict__ out) {
    const int row = blockIdx.x * 8 + (threadIdx.x >> 5);   // row = b*TT + t
    const int lane = threadIdx.x & 31;
    float4 yv = ((const float4*)(g_y1 + (size_t)row * HH))[lane];
    float4 wv = ((const float4*)fc_w)[lane];
    float p = fmaxf(yv.x, 0.f) * wv.x + fmaxf(yv.y, 0.f) * wv.y
            + fmaxf(yv.z, 0.f) * wv.z + fmaxf(yv.w, 0.f) * wv.w;
    p += __shfl_xor_sync(0xffffffffu, p, 16);
    p += __shfl_xor_sync(0xffffffffu, p, 8);
    p += __shfl_xor_sync(0xffffffffu, p, 4);
    p += __shfl_xor_sync(0xffffffffu, p, 2);
    p += __shfl_xor_sync(0xffffffffu, p, 1);
    if (lane == 0) out[row] = p + fc_b[0];
}

extern "C" void kernel_launch(void* const* d_in, const int* in_sizes, int n_in,
                              void* d_out, int out_size) {
    const float* data   = (const float*)d_in[0];
    const float* hidden = (const float*)d_in[1];
    const float* w_ih0  = (const float*)d_in[2];
    const float* w_hh0  = (const float*)d_in[3];
    const float* b_ih0  = (const float*)d_in[4];
    const float* b_hh0  = (const float*)d_in[5];
    const float* w_ih1  = (const float*)d_in[6];
    const float* w_hh1  = (const float*)d_in[7];
    const float* b_ih1  = (const float*)d_in[8];
    const float* b_hh1  = (const float*)d_in[9];
    const float* fc_w   = (const float*)d_in[10];
    const float* fc_b   = (const float*)d_in[11];

    float* out = (float*)d_out;
    float* hT  = out + (size_t)BB * TT;   // [2,B,H] final hidden

    k_main<<<2 * BB + NWORK, 384>>>(data, hidden, w_ih0, w_hh0, b_ih0, b_hh0,
                                    w_ih1, w_hh1, b_ih1, b_hh1, hT);
    k_fc<<<BB * TT / 8, 256>>>(fc_w, fc_b, out);
}

// round 8
// speedup vs baseline: 1.3046x; 1.3046x over previous
#include <cuda_runtime.h>

#define BB 64
#define TT 4096
#define HH 128
#define GG 384   /* 3H */
#define NWORK 84 /* B-worker CTAs; 64 + 84 = 148 = full wave-1 residency */

// Scratch (allocation-free rule: __device__ globals)
__device__ float g_y0[(size_t)BB * TT * HH];    // layer-0 outputs [b][t][k]  128 MiB
__device__ float g_xg1[(size_t)BB * TT * GG];   // layer-1 ih gates [b][t][g] 402 MiB
__device__ float g_y1[(size_t)BB * TT * HH];    // layer-1 outputs [b][t][k]  128 MiB
__device__ int   g_flagA[BB * 32];              // y0 chunk ready  (producer -> worker)
__device__ int   g_flagB[BB * 32];              // xg1 chunk ready (worker -> consumer)

typedef unsigned long long ull;

static __device__ __forceinline__ ull pk(float a, float b) {
    ull r; asm("mov.b64 %0, {%1, %2};" : "=l"(r) : "f"(a), "f"(b)); return r;
}
static __device__ __forceinline__ void upk(ull v, float& a, float& b) {
    asm("mov.b64 {%0, %1}, %2;" : "=f"(a), "=f"(b) : "l"(v));
}
// Packed fp32x2 FMA / ADD (Blackwell): 2 ops per issue slot
static __device__ __forceinline__ void ffma2(ull& acc, ull a, ull b) {
    asm("fma.rn.f32x2 %0, %1, %2, %0;" : "+l"(acc) : "l"(a), "l"(b));
}
static __device__ __forceinline__ ull add2(ull a, ull b) {
    ull r; asm("add.rn.f32x2 %0, %1, %2;" : "=l"(r) : "l"(a), "l"(b)); return r;
}
static __device__ __forceinline__ float tanha(float x) {     // MUFU tanh
    float y; asm("tanh.approx.f32 %0, %1;" : "=f"(y) : "f"(x)); return y;
}
static __device__ __forceinline__ float sigfast(float x) {   // sigmoid via MUFU tanh
    return fmaf(0.5f, tanha(0.5f * x), 0.5f);
}
static __device__ __forceinline__ int ldacq(const int* p) {
    int v; asm volatile("ld.acquire.gpu.global.b32 %0, [%1];" : "=r"(v) : "l"(p) : "memory");
    return v;
}
static __device__ __forceinline__ void strel(int* p, int v) {
    asm volatile("st.release.gpu.global.b32 [%0], %1;" :: "l"(p), "r"(v) : "memory");
}
static __device__ __forceinline__ void stplain(int* p, int v) {
    asm volatile("st.global.b32 [%0], %1;" :: "l"(p), "r"(v) : "memory");
}

// Load one 128-float weight row into 64 packed register pairs.
static __device__ __forceinline__ void loadw(ull* w, const float* __restrict__ row) {
    const float4* r4 = (const float4*)row;
#pragma unroll
    for (int i = 0; i < 32; i++) {
        float4 v = r4[i];
        w[2 * i]     = pk(v.x, v.y);
        w[2 * i + 1] = pk(v.z, v.w);
    }
}

// dot(w_row[128], hsm[128]) with broadcast LDS.128 + packed FMA, 4 acc chains.
static __device__ __forceinline__ float dot128(const ull* w, const float* hsm) {
    const ulonglong2* h2 = (const ulonglong2*)hsm;
    ull a0 = 0, a1 = 0, a2 = 0, a3 = 0;
#pragma unroll
    for (int k = 0; k < 16; k++) {
        ulonglong2 p = h2[2 * k];
        ulonglong2 q = h2[2 * k + 1];
        ffma2(a0, w[4 * k + 0], p.x);
        ffma2(a1, w[4 * k + 1], p.y);
        ffma2(a2, w[4 * k + 2], q.x);
        ffma2(a3, w[4 * k + 3], q.y);
    }
    ull s = add2(add2(a0, a1), add2(a2, a3));
    float x0, x1; upk(s, x0, x1);
    return x0 + x1;
}

// ===== Mega-kernel: 64 recurrence CTAs (layer0 -> role-switch -> layer1)
//       + 84 worker CTAs (xg1 = y0 @ w_ih1.T + b_ih1, chunk-streamed) =====
// Recurrence layout: warp=tid>>5, grp=warp/3, role=warp%3 (0=r,1=z,2=n);
// group g owns units [32g,32g+32); named barrier (g+1) over its 96 threads.
// Pre-bar: role0 computes r=sig(pre) -> s_rz.x, role1 z=sig(pre) -> s_rz.y.
// Post-bar: role2 (holds acc,xi in regs + owns h) does ONE LDS.64 -> tanh ->
// h update -> stores hsm + y. h double-buffered => one block barrier per step.
// Flags reset by their unique consumer => graph-replay safe, no reset kernel.
__global__ void __launch_bounds__(384, 1)
k_main(const float* __restrict__ data, const float* __restrict__ hidden,
       const float* __restrict__ w_ih0, const float* __restrict__ w_hh0,
       const float* __restrict__ b_ih0, const float* __restrict__ b_hh0,
       const float* __restrict__ w_ih1, const float* __restrict__ w_hh1,
       const float* __restrict__ b_ih1, const float* __restrict__ b_hh1,
       float* __restrict__ hT) {
    __shared__ __align__(16) float hsm[2][HH];
    __shared__ __align__(8) float2 s_rz[HH];
    __shared__ __align__(16) float xbuf[512];
    __shared__ __align__(16) float ybuf[8 * HH];

    const int tid = threadIdx.x;

    if (blockIdx.x >= BB) {
        // ---------------- WORKER: xg1 = y0 @ w_ih1.T + b_ih1 ----------------
        const int wk = blockIdx.x - BB;
        ull w[64];
        loadw(w, w_ih1 + tid * HH);
        const float bi = b_ih1[tid];

        for (int task = wk; task < BB * 32; task += NWORK) {
            const int c = task >> 6, b = task & 63;   // chunk-major: fresh y0 in L2
            if (tid == 0) {
                const int* f = g_flagA + b * 32 + c;
                while (ldacq(f) == 0) __nanosleep(64);
            }
            __syncthreads();
            const float* y0 = g_y0 + ((size_t)b * TT + (size_t)c * 128) * HH;
            float* xo = g_xg1 + ((size_t)b * TT + (size_t)c * 128) * GG;
            for (int tt = 0; tt < 128; tt += 8) {
                if (tid < 256) ((float4*)ybuf)[tid] = ((const float4*)(y0 + (size_t)tt * HH))[tid];
                __syncthreads();
#pragma unroll
                for (int r = 0; r < 8; r++) {
                    float acc = dot128(w, ybuf + r * HH);
                    xo[(size_t)(tt + r) * GG + tid] = acc + bi;
                }
                __syncthreads();
            }
            if (tid == 0) {
                stplain(g_flagA + b * 32 + c, 0);     // self-reset for next replay
                strel(g_flagB + b * 32 + c, 1);
            }
        }
        return;
    }

    const int warp = tid >> 5, lane = tid & 31;
    const int grp = warp / 3, role = warp - grp * 3;
    const int unit = (grp << 5) | lane;
    const int row = role * HH + unit;
    const int b = blockIdx.x;

    // ================= PHASE 1: layer-0 recurrence (producer) =================
    {
        ull w[64];
        loadw(w, w_hh0 + row * HH);
        const float wi = w_ih0[row], bi = b_ih0[row], bh = b_hh0[row];

        float h_old = hidden[(size_t)b * HH + unit];   // role2 owns h
        if (role == 2) hsm[0][unit] = h_old;
        __syncthreads();

        const float* xg = data + (size_t)b * TT;
        float* y0 = g_y0 + (size_t)b * TT * HH;
        int* fl = g_flagA + b * 32;

        int cur = 0;
        for (int t = 0; t < TT; t++) {
            if ((t & 511) == 0) {
                if (tid < 128) ((float4*)xbuf)[tid] = ((const float4*)(xg + t))[tid];
                __syncthreads();
            }
            const float x = xbuf[t & 511];
            float acc = dot128(w, hsm[cur]) + bh;
            float xi = fmaf(x, wi, bi);
            if (role == 0)      s_rz[unit].x = sigfast(acc + xi);   // r, pre-bar
            else if (role == 1) s_rz[unit].y = sigfast(acc + xi);   // z, pre-bar
            asm volatile("bar.sync %0, 96;" :: "r"(grp + 1) : "memory");
            if (role == 2) {
                float2 rz = s_rz[unit];                 // single LDS.64
                float n = tanha(fmaf(rz.x, acc, xi));   // acc, xi in regs
                h_old = fmaf(rz.y, h_old - n, n);       // (1-z)n + z h
                hsm[cur ^ 1][unit] = h_old;
                y0[(size_t)t * HH + unit] = h_old;      // ship to workers
            }
            __syncthreads();
            // chunk-granular publish: barrier + release store => visible
            if (((t & 127) == 127) && tid == 0) strel(fl + (t >> 7), 1);
            cur ^= 1;
        }
        if (role == 2) hT[(size_t)b * HH + unit] = h_old;
    }

    // ====== PHASE 2 (role-switch): layer-1 recurrence on the same CTA ======
    __syncthreads();
    {
        ull w[64];
        loadw(w, w_hh1 + row * HH);
        const float bh = b_hh1[row];

        float h_old = hidden[(size_t)BB * HH + (size_t)b * HH + unit];
        if (role == 2) hsm[0][unit] = h_old;   // ordered by first chunk's barrier

        const float* xgp = g_xg1 + (size_t)b * TT * GG + row;
        float* y1 = g_y1 + (size_t)b * TT * HH;
        int* fl = g_flagB + b * 32;

        int cur = 0;
        for (int c = 0; c < 32; c++) {
            if (tid == 0) {
                const int* f = fl + c;
                while (ldacq(f) == 0) __nanosleep(64);
            }
            __syncthreads();
            float xv = xgp[(size_t)(c * 128) * GG];
            for (int tt = 0; tt < 128; tt++) {
                const int t = c * 128 + tt;
                float acc = dot128(w, hsm[cur]) + bh;
                float xnext = (tt < 127) ? xgp[(size_t)(t + 1) * GG] : 0.f;  // prefetch
                if (role == 0)      s_rz[unit].x = sigfast(acc + xv);
                else if (role == 1) s_rz[unit].y = sigfast(acc + xv);
                asm volatile("bar.sync %0, 96;" :: "r"(grp + 1) : "memory");
                if (role == 2) {
                    float2 rz = s_rz[unit];
                    float n = tanha(fmaf(rz.x, acc, xv));
                    h_old = fmaf(rz.y, h_old - n, n);
                    hsm[cur ^ 1][unit] = h_old;
                    y1[(size_t)t * HH + unit] = h_old;   // FC done by tail kernel
                }
                __syncthreads();
                xv = xnext;
                cur ^= 1;
            }
            if (tid == 0) stplain(fl + c, 0);            // self-reset
        }
        if (role == 2) hT[(size_t)BB * HH + (size_t)b * HH + unit] = h_old;
    }
}

// ---------- Tail: out[b,t] = relu(y1[b,t,:]) . fc_w + fc_b  (memory-bound) ----------
__global__ void __launch_bounds__(256)
k_fc(const float* __restrict__ fc_w, const float* __restrict__ fc_b,
     float* __restrict__ out) {
    const int row = blockIdx.x * 8 + (threadIdx.x >> 5);   // row = b*TT + t
    const int lane = threadIdx.x & 31;
    float4 yv = ((const float4*)(g_y1 + (size_t)row * HH))[lane];
    float4 wv = ((const float4*)fc_w)[lane];
    float p = fmaxf(yv.x, 0.f) * wv.x + fmaxf(yv.y, 0.f) * wv.y
            + fmaxf(yv.z, 0.f) * wv.z + fmaxf(yv.w, 0.f) * wv.w;
    p += __shfl_xor_sync(0xffffffffu, p, 16);
    p += __shfl_xor_sync(0xffffffffu, p, 8);
    p += __shfl_xor_sync(0xffffffffu, p, 4);
    p += __shfl_xor_sync(0xffffffffu, p, 2);
    p += __shfl_xor_sync(0xffffffffu, p, 1);
    if (lane == 0) out[row] = p + fc_b[0];
}

extern "C" void kernel_launch(void* const* d_in, const int* in_sizes, int n_in,
                              void* d_out, int out_size) {
    const float* data   = (const float*)d_in[0];
    const float* hidden = (const float*)d_in[1];
    const float* w_ih0  = (const float*)d_in[2];
    const float* w_hh0  = (const float*)d_in[3];
    const float* b_ih0  = (const float*)d_in[4];
    const float* b_hh0  = (const float*)d_in[5];
    const float* w_ih1  = (const float*)d_in[6];
    const float* w_hh1  = (const float*)d_in[7];
    const float* b_ih1  = (const float*)d_in[8];
    const float* b_hh1  = (const float*)d_in[9];
    const float* fc_w   = (const float*)d_in[10];
    const float* fc_b   = (const float*)d_in[11];

    float* out = (float*)d_out;
    float* hT  = out + (size_t)BB * TT;   // [2,B,H] final hidden

    k_main<<<BB + NWORK, 384>>>(data, hidden, w_ih0, w_hh0, b_ih0, b_hh0,
                                w_ih1, w_hh1, b_ih1, b_hh1, hT);
    k_fc<<<BB * TT / 8, 256>>>(fc_w, fc_b, out);
}

// round 9
// speedup vs baseline: 1.5619x; 1.1972x over previous
#include <cuda_runtime.h>

#define BB 64
#define TT 4096
#define HH 128
#define GG 384   /* 3H */
#define NWORK 84 /* B-worker CTAs; 64 + 84 = 148 = full wave-1 residency */

// Scratch (allocation-free rule: __device__ globals)
__device__ float g_y0[(size_t)BB * TT * HH];    // layer-0 outputs [b][t][k]  128 MiB
__device__ float g_xg1[(size_t)BB * TT * GG];   // layer-1 ih gates [b][t][g] 402 MiB
__device__ float g_y1[(size_t)BB * TT * HH];    // layer-1 outputs [b][t][k]  128 MiB
__device__ int   g_flagA[BB * 32];              // y0 chunk ready  (producer -> worker)
__device__ int   g_flagB[BB * 32];              // xg1 chunk ready (worker -> consumer)

typedef unsigned long long ull;

static __device__ __forceinline__ ull pk(float a, float b) {
    ull r; asm("mov.b64 %0, {%1, %2};" : "=l"(r) : "f"(a), "f"(b)); return r;
}
static __device__ __forceinline__ void upk(ull v, float& a, float& b) {
    asm("mov.b64 {%0, %1}, %2;" : "=f"(a), "=f"(b) : "l"(v));
}
// Packed fp32x2 FMA / ADD (Blackwell): 2 ops per issue slot
static __device__ __forceinline__ void ffma2(ull& acc, ull a, ull b) {
    asm("fma.rn.f32x2 %0, %1, %2, %0;" : "+l"(acc) : "l"(a), "l"(b));
}
static __device__ __forceinline__ ull add2(ull a, ull b) {
    ull r; asm("add.rn.f32x2 %0, %1, %2;" : "=l"(r) : "l"(a), "l"(b)); return r;
}
static __device__ __forceinline__ float red2(ull a, ull b) {
    ull s = add2(a, b); float x0, x1; upk(s, x0, x1); return x0 + x1;
}
static __device__ __forceinline__ float tanha(float x) {     // MUFU tanh
    float y; asm("tanh.approx.f32 %0, %1;" : "=f"(y) : "f"(x)); return y;
}
static __device__ __forceinline__ float sigfast(float x) {   // sigmoid via MUFU tanh
    return fmaf(0.5f, tanha(0.5f * x), 0.5f);
}
static __device__ __forceinline__ int ldacq(const int* p) {
    int v; asm volatile("ld.acquire.gpu.global.b32 %0, [%1];" : "=r"(v) : "l"(p) : "memory");
    return v;
}
static __device__ __forceinline__ void strel(int* p, int v) {
    asm volatile("st.release.gpu.global.b32 [%0], %1;" :: "l"(p), "r"(v) : "memory");
}
static __device__ __forceinline__ void stplain(int* p, int v) {
    asm volatile("st.global.b32 [%0], %1;" :: "l"(p), "r"(v) : "memory");
}

// Load one full 128-float weight row into 64 packed pairs (worker path).
static __device__ __forceinline__ void loadw(ull* w, const float* __restrict__ row) {
    const float4* r4 = (const float4*)row;
#pragma unroll
    for (int i = 0; i < 32; i++) {
        float4 v = r4[i];
        w[2 * i]     = pk(v.x, v.y);
        w[2 * i + 1] = pk(v.z, v.w);
    }
}
// Load a 64-float half-row into 32 packed pairs (recurrence path).
static __device__ __forceinline__ void loadw64(ull* w, const float* __restrict__ row) {
    const float4* r4 = (const float4*)row;
#pragma unroll
    for (int i = 0; i < 16; i++) {
        float4 v = r4[i];
        w[2 * i]     = pk(v.x, v.y);
        w[2 * i + 1] = pk(v.z, v.w);
    }
}

// Full dot (worker path): 32 LDS.128 + 64 FFMA2, 4 chains.
static __device__ __forceinline__ float dot128(const ull* w, const float* hsm) {
    const ulonglong2* h2 = (const ulonglong2*)hsm;
    ull a0 = 0, a1 = 0, a2 = 0, a3 = 0;
#pragma unroll
    for (int k = 0; k < 16; k++) {
        ulonglong2 p = h2[2 * k];
        ulonglong2 q = h2[2 * k + 1];
        ffma2(a0, w[4 * k + 0], p.x);
        ffma2(a1, w[4 * k + 1], p.y);
        ffma2(a2, w[4 * k + 2], q.x);
        ffma2(a3, w[4 * k + 3], q.y);
    }
    return red2(add2(a0, a1), add2(a2, a3));
}

// Recurrence dot: this thread's HALF of h (16 LDS.128) feeding TWO adjacent
// rows' half-dots. Returns both half-sums; partner halves come via shfl.
static __device__ __forceinline__ float2 dot2half(const ull* wa, const ull* wb,
                                                  const float* hsm, int hioff16) {
    const ulonglong2* h2 = (const ulonglong2*)hsm + hioff16;   // lo: +0, hi: +16
    ull a0 = 0, a1 = 0, b0 = 0, b1 = 0;
#pragma unroll
    for (int k = 0; k < 16; k++) {
        ulonglong2 q = h2[k];
        ffma2(a0, wa[2 * k],     q.x);
        ffma2(a1, wa[2 * k + 1], q.y);
        ffma2(b0, wb[2 * k],     q.x);
        ffma2(b1, wb[2 * k + 1], q.y);
    }
    return make_float2(red2(a0, a1), red2(b0, b1));
}

// ===== Mega-kernel: 64 recurrence CTAs (layer0 -> role-switch -> layer1)
//       + 84 worker CTAs (xg1 = y0 @ w_ih1.T + b_ih1, chunk-streamed) =====
// Recurrence layout: warp w: role=w>>2 (0=r,1=z,2=n), blk=w&3 owns units
// [32blk,32blk+32). lane l: half=l>>4, k=l&15. Thread computes half-dots of
// rows R0=(role<<7)+(blk<<5)+2k and R0+1 using its h-half; shfl.bfly(16)
// combines halves; lane then owns gate unit u=32blk+2k+half.
// Pre-bar: r/z lanes sigmoid -> s_rz[u].x/.y. Group barrier = named bar blk+1
// over the 3 warps (96 thr). Post-bar: n-lane does LDS.64 -> tanh -> h update.
// h double-buffered => one block barrier per step. Flags self-reset.
__global__ void __launch_bounds__(384, 1)
k_main(const float* __restrict__ data, const float* __restrict__ hidden,
       const float* __restrict__ w_ih0, const float* __restrict__ w_hh0,
       const float* __restrict__ b_ih0, const float* __restrict__ b_hh0,
       const float* __restrict__ w_ih1, const float* __restrict__ w_hh1,
       const float* __restrict__ b_ih1, const float* __restrict__ b_hh1,
       float* __restrict__ hT) {
    __shared__ __align__(16) float hsm[2][HH];
    __shared__ __align__(8) float2 s_rz[HH];
    __shared__ __align__(16) float xbuf[512];
    __shared__ __align__(16) float ybuf[8 * HH];

    const int tid = threadIdx.x;

    if (blockIdx.x >= BB) {
        // ---------------- WORKER: xg1 = y0 @ w_ih1.T + b_ih1 ----------------
        const int wk = blockIdx.x - BB;
        ull w[64];
        loadw(w, w_ih1 + tid * HH);
        const float bi = b_ih1[tid];

        for (int task = wk; task < BB * 32; task += NWORK) {
            const int c = task >> 6, b = task & 63;   // chunk-major: fresh y0 in L2
            if (tid == 0) {
                const int* f = g_flagA + b * 32 + c;
                while (ldacq(f) == 0) __nanosleep(64);
            }
            __syncthreads();
            const float* y0 = g_y0 + ((size_t)b * TT + (size_t)c * 128) * HH;
            float* xo = g_xg1 + ((size_t)b * TT + (size_t)c * 128) * GG;
            for (int tt = 0; tt < 128; tt += 8) {
                if (tid < 256) ((float4*)ybuf)[tid] = ((const float4*)(y0 + (size_t)tt * HH))[tid];
                __syncthreads();
#pragma unroll
                for (int r = 0; r < 8; r++) {
                    float acc = dot128(w, ybuf + r * HH);
                    xo[(size_t)(tt + r) * GG + tid] = acc + bi;
                }
                __syncthreads();
            }
            if (tid == 0) {
                stplain(g_flagA + b * 32 + c, 0);     // self-reset for next replay
                strel(g_flagB + b * 32 + c, 1);
            }
        }
        return;
    }

    const int warp = tid >> 5, lane = tid & 31;
    const int role = warp >> 2;            // 0=r, 1=z, 2=n
    const int blk  = warp & 3;
    const int half = lane >> 4;            // 0=lo h-half, 1=hi h-half
    const int kk   = lane & 15;
    const int unit = (blk << 5) | (kk << 1) | half;   // this lane's gate unit
    const int grow = (role << 7) | unit;              // gate row in [0,384)
    const int R0   = (role << 7) | (blk << 5) | (kk << 1);  // even dot row
    const int hioff = half << 4;           // ulonglong2 offset into h
    const int b = blockIdx.x;

    // ================= PHASE 1: layer-0 recurrence (producer) =================
    {
        ull wa[32], wb[32];
        loadw64(wa, w_hh0 + (size_t)R0 * HH + half * 64);
        loadw64(wb, w_hh0 + (size_t)(R0 + 1) * HH + half * 64);
        const float wi = w_ih0[grow], bi = b_ih0[grow], bh = b_hh0[grow];

        float h_old = hidden[(size_t)b * HH + unit];   // n-lane owns h(unit)
        if (role == 2) hsm[0][unit] = h_old;
        __syncthreads();

        const float* xg = data + (size_t)b * TT;
        float* y0 = g_y0 + (size_t)b * TT * HH;
        int* fl = g_flagA + b * 32;

        int cur = 0;
        for (int t = 0; t < TT; t++) {
            if ((t & 511) == 0) {
                if (tid < 128) ((float4*)xbuf)[tid] = ((const float4*)(xg + t))[tid];
                __syncthreads();
            }
            const float x = xbuf[t & 511];
            float2 p = dot2half(wa, wb, hsm[cur], hioff);
            float o0 = __shfl_xor_sync(0xffffffffu, p.x, 16);
            float o1 = __shfl_xor_sync(0xffffffffu, p.y, 16);
            float acc = (half ? p.y + o1 : p.x + o0) + bh;   // full dot + bias
            float xi = fmaf(x, wi, bi);
            if (role == 0)      s_rz[unit].x = sigfast(acc + xi);   // r, pre-bar
            else if (role == 1) s_rz[unit].y = sigfast(acc + xi);   // z, pre-bar
            asm volatile("bar.sync %0, 96;" :: "r"(blk + 1) : "memory");
            if (role == 2) {
                float2 rz = s_rz[unit];                 // single LDS.64
                float n = tanha(fmaf(rz.x, acc, xi));   // acc, xi in regs
                h_old = fmaf(rz.y, h_old - n, n);       // (1-z)n + z h
                hsm[cur ^ 1][unit] = h_old;
                y0[(size_t)t * HH + unit] = h_old;      // ship to workers
            }
            __syncthreads();
            // chunk-granular publish: barrier + release store => visible
            if (((t & 127) == 127) && tid == 0) strel(fl + (t >> 7), 1);
            cur ^= 1;
        }
        if (role == 2) hT[(size_t)b * HH + unit] = h_old;
    }

    // ====== PHASE 2 (role-switch): layer-1 recurrence on the same CTA ======
    __syncthreads();
    {
        ull wa[32], wb[32];
        loadw64(wa, w_hh1 + (size_t)R0 * HH + half * 64);
        loadw64(wb, w_hh1 + (size_t)(R0 + 1) * HH + half * 64);
        const float bh = b_hh1[grow];

        float h_old = hidden[(size_t)BB * HH + (size_t)b * HH + unit];
        if (role == 2) hsm[0][unit] = h_old;   // ordered by first chunk's barrier

        const float* xgp = g_xg1 + (size_t)b * TT * GG + grow;
        float* y1 = g_y1 + (size_t)b * TT * HH;
        int* fl = g_flagB + b * 32;

        int cur = 0;
        for (int c = 0; c < 32; c++) {
            if (tid == 0) {
                const int* f = fl + c;
                while (ldacq(f) == 0) __nanosleep(64);
            }
            __syncthreads();
            float xv = xgp[(size_t)(c * 128) * GG];
            for (int tt = 0; tt < 128; tt++) {
                const int t = c * 128 + tt;
                float2 p = dot2half(wa, wb, hsm[cur], hioff);
                float xnext = (tt < 127) ? xgp[(size_t)(t + 1) * GG] : 0.f;  // prefetch
                float o0 = __shfl_xor_sync(0xffffffffu, p.x, 16);
                float o1 = __shfl_xor_sync(0xffffffffu, p.y, 16);
                float acc = (half ? p.y + o1 : p.x + o0) + bh;
                if (role == 0)      s_rz[unit].x = sigfast(acc + xv);
                else if (role == 1) s_rz[unit].y = sigfast(acc + xv);
                asm volatile("bar.sync %0, 96;" :: "r"(blk + 1) : "memory");
                if (role == 2) {
                    float2 rz = s_rz[unit];
                    float n = tanha(fmaf(rz.x, acc, xv));
                    h_old = fmaf(rz.y, h_old - n, n);
                    hsm[cur ^ 1][unit] = h_old;
                    y1[(size_t)t * HH + unit] = h_old;   // FC done by tail kernel
                }
                __syncthreads();
                xv = xnext;
                cur ^= 1;
            }
            if (tid == 0) stplain(fl + c, 0);            // self-reset
        }
        if (role == 2) hT[(size_t)BB * HH + (size_t)b * HH + unit] = h_old;
    }
}

// ---------- Tail: out[b,t] = relu(y1[b,t,:]) . fc_w + fc_b  (memory-bound) ----------
__global__ void __launch_bounds__(256)
k_fc(const float* __restrict__ fc_w, const float* __restrict__ fc_b,
     float* __restrict__ out) {
    const int row = blockIdx.x * 8 + (threadIdx.x >> 5);   // row = b*TT + t
    const int lane = threadIdx.x & 31;
    float4 yv = ((const float4*)(g_y1 + (size_t)row * HH))[lane];
    float4 wv = ((const float4*)fc_w)[lane];
    float p = fmaxf(yv.x, 0.f) * wv.x + fmaxf(yv.y, 0.f) * wv.y
            + fmaxf(yv.z, 0.f) * wv.z + fmaxf(yv.w, 0.f) * wv.w;
    p += __shfl_xor_sync(0xffffffffu, p, 16);
    p += __shfl_xor_sync(0xffffffffu, p, 8);
    p += __shfl_xor_sync(0xffffffffu, p, 4);
    p += __shfl_xor_sync(0xffffffffu, p, 2);
    p += __shfl_xor_sync(0xffffffffu, p, 1);
    if (lane == 0) out[row] = p + fc_b[0];
}

extern "C" void kernel_launch(void* const* d_in, const int* in_sizes, int n_in,
                              void* d_out, int out_size) {
    const float* data   = (const float*)d_in[0];
    const float* hidden = (const float*)d_in[1];
    const float* w_ih0  = (const float*)d_in[2];
    const float* w_hh0  = (const float*)d_in[3];
    const float* b_ih0  = (const float*)d_in[4];
    const float* b_hh0  = (const float*)d_in[5];
    const float* w_ih1  = (const float*)d_in[6];
    const float* w_hh1  = (const float*)d_in[7];
    const float* b_ih1  = (const float*)d_in[8];
    const float* b_hh1  = (const float*)d_in[9];
    const float* fc_w   = (const float*)d_in[10];
    const float* fc_b   = (const float*)d_in[11];

    float* out = (float*)d_out;
    float* hT  = out + (size_t)BB * TT;   // [2,B,H] final hidden

    k_main<<<BB + NWORK, 384>>>(data, hidden, w_ih0, w_hh0, b_ih0, b_hh0,
                                w_ih1, w_hh1, b_ih1, b_hh1, hT);
    k_fc<<<BB * TT / 8, 256>>>(fc_w, fc_b, out);
}

// round 10
// speedup vs baseline: 1.5736x; 1.0075x over previous
#include <cuda_runtime.h>

#define BB 64
#define TT 4096
#define HH 128
#define GG 384   /* 3H */
#define NWORK 84 /* B-worker CTAs; 64 + 84 = 148 = full wave-1 residency */

// Scratch (allocation-free rule: __device__ globals)
__device__ float g_y0[(size_t)BB * TT * HH];    // layer-0 outputs [b][t][k]  128 MiB
__device__ float g_xg1[(size_t)BB * TT * GG];   // layer-1 ih gates [b][t][g] 402 MiB
__device__ float g_y1[(size_t)BB * TT * HH];    // layer-1 outputs [b][t][k]  128 MiB
__device__ int   g_flagA[BB * 32];              // y0 chunk ready  (producer -> worker)
__device__ int   g_flagB[BB * 32];              // xg1 chunk ready (worker -> consumer)

typedef unsigned long long ull;

static __device__ __forceinline__ ull pk(float a, float b) {
    ull r; asm("mov.b64 %0, {%1, %2};" : "=l"(r) : "f"(a), "f"(b)); return r;
}
static __device__ __forceinline__ void upk(ull v, float& a, float& b) {
    asm("mov.b64 {%0, %1}, %2;" : "=f"(a), "=f"(b) : "l"(v));
}
// Packed fp32x2 FMA / ADD (Blackwell): 2 ops per issue slot
static __device__ __forceinline__ void ffma2(ull& acc, ull a, ull b) {
    asm("fma.rn.f32x2 %0, %1, %2, %0;" : "+l"(acc) : "l"(a), "l"(b));
}
static __device__ __forceinline__ ull add2(ull a, ull b) {
    ull r; asm("add.rn.f32x2 %0, %1, %2;" : "=l"(r) : "l"(a), "l"(b)); return r;
}
static __device__ __forceinline__ float red2(ull a, ull b) {
    ull s = add2(a, b); float x0, x1; upk(s, x0, x1); return x0 + x1;
}
static __device__ __forceinline__ float tanha(float x) {     // MUFU tanh
    float y; asm("tanh.approx.f32 %0, %1;" : "=f"(y) : "f"(x)); return y;
}
static __device__ __forceinline__ float sigfast(float x) {   // sigmoid via MUFU tanh
    return fmaf(0.5f, tanha(0.5f * x), 0.5f);
}
static __device__ __forceinline__ int ldacq(const int* p) {
    int v; asm volatile("ld.acquire.gpu.global.b32 %0, [%1];" : "=r"(v) : "l"(p) : "memory");
    return v;
}
static __device__ __forceinline__ void strel(int* p, int v) {
    asm volatile("st.release.gpu.global.b32 [%0], %1;" :: "l"(p), "r"(v) : "memory");
}
static __device__ __forceinline__ void stplain(int* p, int v) {
    asm volatile("st.global.b32 [%0], %1;" :: "l"(p), "r"(v) : "memory");
}

// Load one full 128-float weight row into 64 packed pairs (worker path).
static __device__ __forceinline__ void loadw(ull* w, const float* __restrict__ row) {
    const float4* r4 = (const float4*)row;
#pragma unroll
    for (int i = 0; i < 32; i++) {
        float4 v = r4[i];
        w[2 * i]     = pk(v.x, v.y);
        w[2 * i + 1] = pk(v.z, v.w);
    }
}
// Load a 32-float quarter-row into 16 packed pairs (recurrence path).
static __device__ __forceinline__ void loadw32(ull* w, const float* __restrict__ row) {
    const float4* r4 = (const float4*)row;
#pragma unroll
    for (int i = 0; i < 8; i++) {
        float4 v = r4[i];
        w[2 * i]     = pk(v.x, v.y);
        w[2 * i + 1] = pk(v.z, v.w);
    }
}

// Full dot (worker path): 32 LDS.128 + 64 FFMA2, 4 chains.
static __device__ __forceinline__ float dot128(const ull* w, const float* hsm) {
    const ulonglong2* h2 = (const ulonglong2*)hsm;
    ull a0 = 0, a1 = 0, a2 = 0, a3 = 0;
#pragma unroll
    for (int k = 0; k < 16; k++) {
        ulonglong2 p = h2[2 * k];
        ulonglong2 q = h2[2 * k + 1];
        ffma2(a0, w[4 * k + 0], p.x);
        ffma2(a1, w[4 * k + 1], p.y);
        ffma2(a2, w[4 * k + 2], q.x);
        ffma2(a3, w[4 * k + 3], q.y);
    }
    return red2(add2(a0, a1), add2(a2, a3));
}

// Recurrence dot: this thread's QUARTER of h (8 LDS.128) feeding FOUR adjacent
// rows' quarter-dots (4 independent chains, 16 FFMA2 each).
static __device__ __forceinline__ void dot4q(const ull w[4][16], const float* hsm,
                                             int qoff8, float* v) {
    const ulonglong2* h2 = (const ulonglong2*)hsm + qoff8;   // quarter q: +8q
    ull a0 = 0, a1 = 0, a2 = 0, a3 = 0;
#pragma unroll
    for (int k = 0; k < 8; k++) {
        ulonglong2 q = h2[k];
        ffma2(a0, w[0][2 * k], q.x); ffma2(a0, w[0][2 * k + 1], q.y);
        ffma2(a1, w[1][2 * k], q.x); ffma2(a1, w[1][2 * k + 1], q.y);
        ffma2(a2, w[2][2 * k], q.x); ffma2(a2, w[2][2 * k + 1], q.y);
        ffma2(a3, w[3][2 * k], q.x); ffma2(a3, w[3][2 * k + 1], q.y);
    }
    float x0, x1;
    upk(a0, x0, x1); v[0] = x0 + x1;
    upk(a1, x0, x1); v[1] = x0 + x1;
    upk(a2, x0, x1); v[2] = x0 + x1;
    upk(a3, x0, x1); v[3] = x0 + x1;
}

// Combine 4 quarter-dots across lanes {j, j+8, j+16, j+24} (2 butterfly
// rounds). Lane (q1,q0) ends with the FULL dot of row base+4j+2*q1+q0.
static __device__ __forceinline__ float combine4(const float* v, int q0, int q1) {
    float s_lo = q0 ? v[0] : v[1];     // send: row i0 != q0
    float k_lo = q0 ? v[1] : v[0];     // keep: row i = q0
    float s_hi = q0 ? v[2] : v[3];
    float k_hi = q0 ? v[3] : v[2];
    float u0 = k_lo + __shfl_xor_sync(0xffffffffu, s_lo, 8);   // row q0 (half)
    float u1 = k_hi + __shfl_xor_sync(0xffffffffu, s_hi, 8);   // row 2+q0 (half)
    float s2 = q1 ? u0 : u1;
    float k2 = q1 ? u1 : u0;
    return k2 + __shfl_xor_sync(0xffffffffu, s2, 16);          // row 2*q1+q0 (full)
}

// ===== Mega-kernel: 64 recurrence CTAs (layer0 -> role-switch -> layer1)
//       + 84 worker CTAs (xg1 = y0 @ w_ih1.T + b_ih1, chunk-streamed) =====
// Recurrence layout: warp w: role=w>>2 (0=r,1=z,2=n), blk=w&3 owns units
// [32blk,32blk+32). lane: q=lane>>3 (h quarter), j=lane&7. Thread computes
// quarter-dots of rows base+4j..4j+3 (base=(role<<7)|(blk<<5)); combine4
// routes row 2*q1+q0 to this lane => lane owns unit (blk<<5)|(j<<2)|(q1<<1)|q0.
// Pre-bar: r/z lanes sigmoid -> s_rz[u].x/.y; named bar blk+1 over 96 thr.
// Post-bar: n-lane does ONE LDS.64 -> tanh -> h update. h double-buffered =>
// one block barrier per step. Flags reset by their unique consumer.
__global__ void __launch_bounds__(384, 1)
k_main(const float* __restrict__ data, const float* __restrict__ hidden,
       const float* __restrict__ w_ih0, const float* __restrict__ w_hh0,
       const float* __restrict__ b_ih0, const float* __restrict__ b_hh0,
       const float* __restrict__ w_ih1, const float* __restrict__ w_hh1,
       const float* __restrict__ b_ih1, const float* __restrict__ b_hh1,
       float* __restrict__ hT) {
    __shared__ __align__(16) float hsm[2][HH];
    __shared__ __align__(8) float2 s_rz[HH];
    __shared__ __align__(16) float xbuf[512];
    __shared__ __align__(16) float ybuf[8 * HH];

    const int tid = threadIdx.x;

    if (blockIdx.x >= BB) {
        // ---------------- WORKER: xg1 = y0 @ w_ih1.T + b_ih1 ----------------
        const int wk = blockIdx.x - BB;
        ull w[64];
        loadw(w, w_ih1 + tid * HH);
        const float bi = b_ih1[tid];

        for (int task = wk; task < BB * 32; task += NWORK) {
            const int c = task >> 6, b = task & 63;   // chunk-major: fresh y0 in L2
            if (tid == 0) {
                const int* f = g_flagA + b * 32 + c;
                while (ldacq(f) == 0) __nanosleep(64);
            }
            __syncthreads();
            const float* y0 = g_y0 + ((size_t)b * TT + (size_t)c * 128) * HH;
            float* xo = g_xg1 + ((size_t)b * TT + (size_t)c * 128) * GG;
            for (int tt = 0; tt < 128; tt += 8) {
                if (tid < 256) ((float4*)ybuf)[tid] = ((const float4*)(y0 + (size_t)tt * HH))[tid];
                __syncthreads();
#pragma unroll
                for (int r = 0; r < 8; r++) {
                    float acc = dot128(w, ybuf + r * HH);
                    xo[(size_t)(tt + r) * GG + tid] = acc + bi;
                }
                __syncthreads();
            }
            if (tid == 0) {
                stplain(g_flagA + b * 32 + c, 0);     // self-reset for next replay
                strel(g_flagB + b * 32 + c, 1);
            }
        }
        return;
    }

    const int warp = tid >> 5, lane = tid & 31;
    const int role = warp >> 2;            // 0=r, 1=z, 2=n
    const int blk  = warp & 3;
    const int q    = lane >> 3;            // h quarter 0..3
    const int q0   = q & 1, q1 = q >> 1;
    const int j    = lane & 7;
    const int base = (role << 7) | (blk << 5) | (j << 2);   // first of 4 dot rows
    const int unit = (blk << 5) | (j << 2) | (q1 << 1) | q0; // lane's gate unit
    const int grow = (role << 7) | unit;                     // gate row in [0,384)
    const int qoff8 = q << 3;              // ulonglong2 offset of h quarter
    const int b = blockIdx.x;

    // ================= PHASE 1: layer-0 recurrence (producer) =================
    {
        ull w[4][16];
#pragma unroll
        for (int r = 0; r < 4; r++)
            loadw32(w[r], w_hh0 + (size_t)(base + r) * HH + q * 32);
        const float wi = w_ih0[grow], bi = b_ih0[grow], bh = b_hh0[grow];

        float h_old = hidden[(size_t)b * HH + unit];   // n-lane owns h(unit)
        if (role == 2) hsm[0][unit] = h_old;
        __syncthreads();

        const float* xg = data + (size_t)b * TT;
        float* y0 = g_y0 + (size_t)b * TT * HH;
        int* fl = g_flagA + b * 32;

        int cur = 0;
        for (int t = 0; t < TT; t++) {
            if ((t & 511) == 0) {
                if (tid < 128) ((float4*)xbuf)[tid] = ((const float4*)(xg + t))[tid];
                __syncthreads();
            }
            const float x = xbuf[t & 511];
            float v[4];
            dot4q(w, hsm[cur], qoff8, v);
            float acc = combine4(v, q0, q1) + bh;            // full dot + bias
            float xi = fmaf(x, wi, bi);
            if (role == 0)      s_rz[unit].x = sigfast(acc + xi);   // r, pre-bar
            else if (role == 1) s_rz[unit].y = sigfast(acc + xi);   // z, pre-bar
            asm volatile("bar.sync %0, 96;" :: "r"(blk + 1) : "memory");
            if (role == 2) {
                float2 rz = s_rz[unit];                 // single LDS.64
                float n = tanha(fmaf(rz.x, acc, xi));   // acc, xi in regs
                h_old = fmaf(rz.y, h_old - n, n);       // (1-z)n + z h
                hsm[cur ^ 1][unit] = h_old;
                y0[(size_t)t * HH + unit] = h_old;      // ship to workers
            }
            __syncthreads();
            // chunk-granular publish: barrier + release store => visible
            if (((t & 127) == 127) && tid == 0) strel(fl + (t >> 7), 1);
            cur ^= 1;
        }
        if (role == 2) hT[(size_t)b * HH + unit] = h_old;
    }

    // ====== PHASE 2 (role-switch): layer-1 recurrence on the same CTA ======
    __syncthreads();
    {
        ull w[4][16];
#pragma unroll
        for (int r = 0; r < 4; r++)
            loadw32(w[r], w_hh1 + (size_t)(base + r) * HH + q * 32);
        const float bh = b_hh1[grow];

        float h_old = hidden[(size_t)BB * HH + (size_t)b * HH + unit];
        if (role == 2) hsm[0][unit] = h_old;   // ordered by first chunk's barrier

        const float* xgp = g_xg1 + (size_t)b * TT * GG + grow;
        float* y1 = g_y1 + (size_t)b * TT * HH;
        int* fl = g_flagB + b * 32;

        int cur = 0;
        for (int c = 0; c < 32; c++) {
            if (tid == 0) {
                const int* f = fl + c;
                while (ldacq(f) == 0) __nanosleep(64);
            }
            __syncthreads();
            float xv = xgp[(size_t)(c * 128) * GG];
            for (int tt = 0; tt < 128; tt++) {
                const int t = c * 128 + tt;
                // issue next x load FIRST so its latency hides under the dot
                float xnext = (tt < 127) ? xgp[(size_t)(t + 1) * GG] : 0.f;
                float v[4];
                dot4q(w, hsm[cur], qoff8, v);
                float acc = combine4(v, q0, q1) + bh;
                if (role == 0)      s_rz[unit].x = sigfast(acc + xv);
                else if (role == 1) s_rz[unit].y = sigfast(acc + xv);
                asm volatile("bar.sync %0, 96;" :: "r"(blk + 1) : "memory");
                if (role == 2) {
                    float2 rz = s_rz[unit];
                    float n = tanha(fmaf(rz.x, acc, xv));
                    h_old = fmaf(rz.y, h_old - n, n);
                    hsm[cur ^ 1][unit] = h_old;
                    y1[(size_t)t * HH + unit] = h_old;   // FC done by tail kernel
                }
                __syncthreads();
                xv = xnext;
                cur ^= 1;
            }
            if (tid == 0) stplain(fl + c, 0);            // self-reset
        }
        if (role == 2) hT[(size_t)BB * HH + (size_t)b * HH + unit] = h_old;
    }
}

// ---------- Tail: out[b,t] = relu(y1[b,t,:]) . fc_w + fc_b  (memory-bound) ----------
__global__ void __launch_bounds__(256)
k_fc(const float* __restrict__ fc_w, const float* __restrict__ fc_b,
     float* __restrict__ out) {
    const int row = blockIdx.x * 8 + (threadIdx.x >> 5);   // row = b*TT + t
    const int lane = threadIdx.x & 31;
    float4 yv = ((const float4*)(g_y1 + (size_t)row * HH))[lane];
    float4 wv = ((const float4*)fc_w)[lane];
    float p = fmaxf(yv.x, 0.f) * wv.x + fmaxf(yv.y, 0.f) * wv.y
            + fmaxf(yv.z, 0.f) * wv.z + fmaxf(yv.w, 0.f) * wv.w;
    p += __shfl_xor_sync(0xffffffffu, p, 16);
    p += __shfl_xor_sync(0xffffffffu, p, 8);
    p += __shfl_xor_sync(0xffffffffu, p, 4);
    p += __shfl_xor_sync(0xffffffffu, p, 2);
    p += __shfl_xor_sync(0xffffffffu, p, 1);
    if (lane == 0) out[row] = p + fc_b[0];
}

extern "C" void kernel_launch(void* const* d_in, const int* in_sizes, int n_in,
                              void* d_out, int out_size) {
    const float* data   = (const float*)d_in[0];
    const float* hidden = (const float*)d_in[1];
    const float* w_ih0  = (const float*)d_in[2];
    const float* w_hh0  = (const float*)d_in[3];
    const float* b_ih0  = (const float*)d_in[4];
    const float* b_hh0  = (const float*)d_in[5];
    const float* w_ih1  = (const float*)d_in[6];
    const float* w_hh1  = (const float*)d_in[7];
    const float* b_ih1  = (const float*)d_in[8];
    const float* b_hh1  = (const float*)d_in[9];
    const float* fc_w   = (const float*)d_in[10];
    const float* fc_b   = (const float*)d_in[11];

    float* out = (float*)d_out;
    float* hT  = out + (size_t)BB * TT;   // [2,B,H] final hidden

    k_main<<<BB + NWORK, 384>>>(data, hidden, w_ih0, w_hh0, b_ih0, b_hh0,
                                w_ih1, w_hh1, b_ih1, b_hh1, hT);
    k_fc<<<BB * TT / 8, 256>>>(fc_w, fc_b, out);
}

// round 11
// speedup vs baseline: 1.7809x; 1.1317x over previous
#include <cuda_runtime.h>

#define BB 64
#define TT 4096
#define HH 128
#define GG 384    /* 3H */
#define NPAIR 32  /* producer/consumer CTAs each handle 2 batches */
#define NWORK 84  /* GEMM workers; 32+32+84 = 148 = full wave-1 residency */

// Scratch (allocation-free rule: __device__ globals)
__device__ float g_y0[(size_t)BB * TT * HH];    // layer-0 outputs [b][t][k]  128 MiB
__device__ float g_xg1[(size_t)BB * TT * GG];   // layer-1 ih gates [b][t][g] 402 MiB
__device__ float g_y1[(size_t)BB * TT * HH];    // layer-1 outputs [b][t][k]  128 MiB
__device__ int   g_flagA[BB * 32];              // y0 chunk ready  (producer -> worker)
__device__ int   g_flagB[BB * 32];              // xg1 chunk ready (worker -> consumer)

typedef unsigned long long ull;

static __device__ __forceinline__ ull pk(float a, float b) {
    ull r; asm("mov.b64 %0, {%1, %2};" : "=l"(r) : "f"(a), "f"(b)); return r;
}
static __device__ __forceinline__ void upk(ull v, float& a, float& b) {
    asm("mov.b64 {%0, %1}, %2;" : "=f"(a), "=f"(b) : "l"(v));
}
// Packed fp32x2 FMA / ADD (Blackwell): 2 ops per issue slot
static __device__ __forceinline__ void ffma2(ull& acc, ull a, ull b) {
    asm("fma.rn.f32x2 %0, %1, %2, %0;" : "+l"(acc) : "l"(a), "l"(b));
}
static __device__ __forceinline__ ull add2(ull a, ull b) {
    ull r; asm("add.rn.f32x2 %0, %1, %2;" : "=l"(r) : "l"(a), "l"(b)); return r;
}
static __device__ __forceinline__ float red2(ull a, ull b) {
    ull s = add2(a, b); float x0, x1; upk(s, x0, x1); return x0 + x1;
}
static __device__ __forceinline__ float tanha(float x) {     // MUFU tanh
    float y; asm("tanh.approx.f32 %0, %1;" : "=f"(y) : "f"(x)); return y;
}
static __device__ __forceinline__ float sigfast(float x) {   // sigmoid via MUFU tanh
    return fmaf(0.5f, tanha(0.5f * x), 0.5f);
}
static __device__ __forceinline__ int ldacq(const int* p) {
    int v; asm volatile("ld.acquire.gpu.global.b32 %0, [%1];" : "=r"(v) : "l"(p) : "memory");
    return v;
}
static __device__ __forceinline__ void strel(int* p, int v) {
    asm volatile("st.release.gpu.global.b32 [%0], %1;" :: "l"(p), "r"(v) : "memory");
}
static __device__ __forceinline__ void stplain(int* p, int v) {
    asm volatile("st.global.b32 [%0], %1;" :: "l"(p), "r"(v) : "memory");
}

// Load one full 128-float weight row into 64 packed pairs (worker path).
static __device__ __forceinline__ void loadw(ull* w, const float* __restrict__ row) {
    const float4* r4 = (const float4*)row;
#pragma unroll
    for (int i = 0; i < 32; i++) {
        float4 v = r4[i];
        w[2 * i]     = pk(v.x, v.y);
        w[2 * i + 1] = pk(v.z, v.w);
    }
}
// Load a 32-float quarter-row into 16 packed pairs (recurrence path).
static __device__ __forceinline__ void loadw32(ull* w, const float* __restrict__ row) {
    const float4* r4 = (const float4*)row;
#pragma unroll
    for (int i = 0; i < 8; i++) {
        float4 v = r4[i];
        w[2 * i]     = pk(v.x, v.y);
        w[2 * i + 1] = pk(v.z, v.w);
    }
}

// Full dot (worker path): 32 LDS.128 + 64 FFMA2, 4 chains.
static __device__ __forceinline__ float dot128(const ull* w, const float* hsm) {
    const ulonglong2* h2 = (const ulonglong2*)hsm;
    ull a0 = 0, a1 = 0, a2 = 0, a3 = 0;
#pragma unroll
    for (int k = 0; k < 16; k++) {
        ulonglong2 p = h2[2 * k];
        ulonglong2 q = h2[2 * k + 1];
        ffma2(a0, w[4 * k + 0], p.x);
        ffma2(a1, w[4 * k + 1], p.y);
        ffma2(a2, w[4 * k + 2], q.x);
        ffma2(a3, w[4 * k + 3], q.y);
    }
    return red2(add2(a0, a1), add2(a2, a3));
}

// Recurrence dot: this thread's QUARTER of h (8 LDS.128) feeding FOUR adjacent
// rows' quarter-dots (4 independent chains, 16 FFMA2 each).
static __device__ __forceinline__ void dot4q(const ull w[4][16], const float* hsm,
                                             int qoff8, float* v) {
    const ulonglong2* h2 = (const ulonglong2*)hsm + qoff8;   // quarter q: +8q
    ull a0 = 0, a1 = 0, a2 = 0, a3 = 0;
#pragma unroll
    for (int k = 0; k < 8; k++) {
        ulonglong2 q = h2[k];
        ffma2(a0, w[0][2 * k], q.x); ffma2(a0, w[0][2 * k + 1], q.y);
        ffma2(a1, w[1][2 * k], q.x); ffma2(a1, w[1][2 * k + 1], q.y);
        ffma2(a2, w[2][2 * k], q.x); ffma2(a2, w[2][2 * k + 1], q.y);
        ffma2(a3, w[3][2 * k], q.x); ffma2(a3, w[3][2 * k + 1], q.y);
    }
    float x0, x1;
    upk(a0, x0, x1); v[0] = x0 + x1;
    upk(a1, x0, x1); v[1] = x0 + x1;
    upk(a2, x0, x1); v[2] = x0 + x1;
    upk(a3, x0, x1); v[3] = x0 + x1;
}

// Combine 4 quarter-dots across lanes {j, j+8, j+16, j+24} (2 butterfly
// rounds). Lane (q1,q0) ends with the FULL dot of row base+4j+2*q1+q0.
static __device__ __forceinline__ float combine4(const float* v, int q0, int q1) {
    float s_lo = q0 ? v[0] : v[1];
    float k_lo = q0 ? v[1] : v[0];
    float s_hi = q0 ? v[2] : v[3];
    float k_hi = q0 ? v[3] : v[2];
    float u0 = k_lo + __shfl_xor_sync(0xffffffffu, s_lo, 8);
    float u1 = k_hi + __shfl_xor_sync(0xffffffffu, s_hi, 8);
    float s2 = q1 ? u0 : u1;
    float k2 = q1 ? u1 : u0;
    return k2 + __shfl_xor_sync(0xffffffffu, s2, 16);
}

// ===== Wavefront mega-kernel with 2-batch-interleaved recurrences =====
//   CTA 0..31  : layer-0 producer for batches (2k, 2k+1)
//   CTA 32..63 : layer-1 consumer for batches (2k, 2k+1), chunk-gated on flagB
//   CTA 64..147: 84 GEMM workers (flagA -> xg1 chunk -> flagB)
// Both batches of a pair share the SAME weight registers; their two serial
// streams interleave so barriers/chains/latency amortize across batches.
// Recurrence layout per warp w: role=w>>2 (0=r,1=z,2=n), blk=w&3; lane:
// q=lane>>3 (h quarter), j=lane&7; thread does quarter-dots of rows
// base+4j..4j+3 per batch; combine4 routes row (q1,q0) to this lane =>
// lane owns unit (blk<<5)|(j<<2)|(q1<<1)|q0. One named bar (96 thr) + one
// __syncthreads per superstep. Flags reset by their unique consumer.
__global__ void __launch_bounds__(384, 1)
k_main(const float* __restrict__ data, const float* __restrict__ hidden,
       const float* __restrict__ w_ih0, const float* __restrict__ w_hh0,
       const float* __restrict__ b_ih0, const float* __restrict__ b_hh0,
       const float* __restrict__ w_ih1, const float* __restrict__ w_hh1,
       const float* __restrict__ b_ih1, const float* __restrict__ b_hh1,
       float* __restrict__ hT) {
    __shared__ __align__(16) float hsm[2][2][HH];    // [buf][batch][unit]
    __shared__ __align__(8) float2 s_rz[2][HH];      // [batch][unit]
    __shared__ __align__(16) float ybuf[8 * HH];

    const int tid = threadIdx.x;

    if (blockIdx.x >= 2 * NPAIR) {
        // ---------------- WORKER: xg1 = y0 @ w_ih1.T + b_ih1 ----------------
        const int wk = blockIdx.x - 2 * NPAIR;
        ull w[64];
        loadw(w, w_ih1 + tid * HH);
        const float bi = b_ih1[tid];

        for (int task = wk; task < BB * 32; task += NWORK) {
            const int c = task >> 6, b = task & 63;   // chunk-major = production order
            if (tid == 0) {
                const int* f = g_flagA + b * 32 + c;
                while (ldacq(f) == 0) __nanosleep(64);
            }
            __syncthreads();
            const float* y0 = g_y0 + ((size_t)b * TT + (size_t)c * 128) * HH;
            float* xo = g_xg1 + ((size_t)b * TT + (size_t)c * 128) * GG;
            for (int tt = 0; tt < 128; tt += 8) {
                if (tid < 256) ((float4*)ybuf)[tid] = ((const float4*)(y0 + (size_t)tt * HH))[tid];
                __syncthreads();
#pragma unroll
                for (int r = 0; r < 8; r++) {
                    float acc = dot128(w, ybuf + r * HH);
                    xo[(size_t)(tt + r) * GG + tid] = acc + bi;
                }
                __syncthreads();
            }
            if (tid == 0) {
                stplain(g_flagA + b * 32 + c, 0);     // self-reset for next replay
                strel(g_flagB + b * 32 + c, 1);
            }
        }
        return;
    }

    const int warp = tid >> 5, lane = tid & 31;
    const int role = warp >> 2;            // 0=r, 1=z, 2=n
    const int blk  = warp & 3;
    const int q    = lane >> 3;
    const int q0   = q & 1, q1 = q >> 1;
    const int j    = lane & 7;
    const int base = (role << 7) | (blk << 5) | (j << 2);
    const int unit = (blk << 5) | (j << 2) | (q1 << 1) | q0;
    const int grow = (role << 7) | unit;
    const int qoff8 = q << 3;

    if (blockIdx.x < NPAIR) {
        // ======== PRODUCER: layer-0 recurrence, batches b0=2k, b1=2k+1 ========
        const int b0 = 2 * blockIdx.x, b1 = b0 + 1;
        ull w[4][16];
#pragma unroll
        for (int r = 0; r < 4; r++)
            loadw32(w[r], w_hh0 + (size_t)(base + r) * HH + q * 32);
        const float wi = w_ih0[grow], bi = b_ih0[grow], bh = b_hh0[grow];

        float h0 = hidden[(size_t)b0 * HH + unit];
        float h1 = hidden[(size_t)b1 * HH + unit];
        if (role == 2) { hsm[0][0][unit] = h0; hsm[0][1][unit] = h1; }
        __syncthreads();

        const float* xg0 = data + (size_t)b0 * TT;
        const float* xg1 = data + (size_t)b1 * TT;
        float* y00 = g_y0 + (size_t)b0 * TT * HH;
        float* y01 = g_y0 + (size_t)b1 * TT * HH;
        int* flA0 = g_flagA + b0 * 32;
        int* flA1 = g_flagA + b1 * 32;

        int cur = 0;
        float x0 = xg0[0], x1 = xg1[0];
        for (int t = 0; t < TT; t++) {
            // prefetch next x (sequential, L1-resident after first touch)
            float xn0 = (t + 1 < TT) ? xg0[t + 1] : 0.f;
            float xn1 = (t + 1 < TT) ? xg1[t + 1] : 0.f;
            float v0[4], v1[4];
            dot4q(w, hsm[cur][0], qoff8, v0);
            dot4q(w, hsm[cur][1], qoff8, v1);
            float acc0 = combine4(v0, q0, q1) + bh;
            float acc1 = combine4(v1, q0, q1) + bh;
            float xi0 = fmaf(x0, wi, bi);
            float xi1 = fmaf(x1, wi, bi);
            if (role == 0) {
                s_rz[0][unit].x = sigfast(acc0 + xi0);
                s_rz[1][unit].x = sigfast(acc1 + xi1);
            } else if (role == 1) {
                s_rz[0][unit].y = sigfast(acc0 + xi0);
                s_rz[1][unit].y = sigfast(acc1 + xi1);
            }
            asm volatile("bar.sync %0, 96;" :: "r"(blk + 1) : "memory");
            if (role == 2) {
                float2 rz0 = s_rz[0][unit];
                float2 rz1 = s_rz[1][unit];
                float n0 = tanha(fmaf(rz0.x, acc0, xi0));
                float n1 = tanha(fmaf(rz1.x, acc1, xi1));
                h0 = fmaf(rz0.y, h0 - n0, n0);
                h1 = fmaf(rz1.y, h1 - n1, n1);
                hsm[cur ^ 1][0][unit] = h0;
                hsm[cur ^ 1][1][unit] = h1;
                y00[(size_t)t * HH + unit] = h0;
                y01[(size_t)t * HH + unit] = h1;
            }
            __syncthreads();
            if (((t & 127) == 127) && tid == 0) {   // publish both chunks
                strel(flA0 + (t >> 7), 1);
                strel(flA1 + (t >> 7), 1);
            }
            x0 = xn0; x1 = xn1;
            cur ^= 1;
        }
        if (role == 2) {
            hT[(size_t)b0 * HH + unit] = h0;
            hT[(size_t)b1 * HH + unit] = h1;
        }
    } else {
        // ======== CONSUMER: layer-1 recurrence, batches b0=2k, b1=2k+1 ========
        const int pid = blockIdx.x - NPAIR;
        const int b0 = 2 * pid, b1 = b0 + 1;
        ull w[4][16];
#pragma unroll
        for (int r = 0; r < 4; r++)
            loadw32(w[r], w_hh1 + (size_t)(base + r) * HH + q * 32);
        const float bh = b_hh1[grow];

        float h0 = hidden[(size_t)(BB + b0) * HH + unit];
        float h1 = hidden[(size_t)(BB + b1) * HH + unit];
        if (role == 2) { hsm[0][0][unit] = h0; hsm[0][1][unit] = h1; }

        const float* xgp0 = g_xg1 + (size_t)b0 * TT * GG + grow;
        const float* xgp1 = g_xg1 + (size_t)b1 * TT * GG + grow;
        float* y10 = g_y1 + (size_t)b0 * TT * HH;
        float* y11 = g_y1 + (size_t)b1 * TT * HH;
        int* flB0 = g_flagB + b0 * 32;
        int* flB1 = g_flagB + b1 * 32;

        int cur = 0;
        for (int c = 0; c < 32; c++) {
            if (tid == 0) {
                while (ldacq(flB0 + c) == 0) __nanosleep(64);
                while (ldacq(flB1 + c) == 0) __nanosleep(64);
            }
            __syncthreads();     // also orders initial hsm write before 1st dot
            float x0 = xgp0[(size_t)(c * 128) * GG];
            float x1 = xgp1[(size_t)(c * 128) * GG];
            for (int tt = 0; tt < 128; tt++) {
                const int t = c * 128 + tt;
                // issue next-x loads FIRST so latency hides under the dots
                float xn0 = (tt < 127) ? xgp0[(size_t)(t + 1) * GG] : 0.f;
                float xn1 = (tt < 127) ? xgp1[(size_t)(t + 1) * GG] : 0.f;
                float v0[4], v1[4];
                dot4q(w, hsm[cur][0], qoff8, v0);
                dot4q(w, hsm[cur][1], qoff8, v1);
                float acc0 = combine4(v0, q0, q1) + bh;
                float acc1 = combine4(v1, q0, q1) + bh;
                if (role == 0) {
                    s_rz[0][unit].x = sigfast(acc0 + x0);
                    s_rz[1][unit].x = sigfast(acc1 + x1);
                } else if (role == 1) {
                    s_rz[0][unit].y = sigfast(acc0 + x0);
                    s_rz[1][unit].y = sigfast(acc1 + x1);
                }
                asm volatile("bar.sync %0, 96;" :: "r"(blk + 1) : "memory");
                if (role == 2) {
                    float2 rz0 = s_rz[0][unit];
                    float2 rz1 = s_rz[1][unit];
                    float n0 = tanha(fmaf(rz0.x, acc0, x0));
                    float n1 = tanha(fmaf(rz1.x, acc1, x1));
                    h0 = fmaf(rz0.y, h0 - n0, n0);
                    h1 = fmaf(rz1.y, h1 - n1, n1);
                    hsm[cur ^ 1][0][unit] = h0;
                    hsm[cur ^ 1][1][unit] = h1;
                    y10[(size_t)t * HH + unit] = h0;
                    y11[(size_t)t * HH + unit] = h1;
                }
                __syncthreads();
                x0 = xn0; x1 = xn1;
                cur ^= 1;
            }
            if (tid == 0) {                     // self-reset for next replay
                stplain(flB0 + c, 0);
                stplain(flB1 + c, 0);
            }
        }
        if (role == 2) {
            hT[(size_t)(BB + b0) * HH + unit] = h0;
            hT[(size_t)(BB + b1) * HH + unit] = h1;
        }
    }
}

// ---------- Tail: out[b,t] = relu(y1[b,t,:]) . fc_w + fc_b  (memory-bound) ----------
__global__ void __launch_bounds__(256)
k_fc(const float* __restrict__ fc_w, const float* __restrict__ fc_b,
     float* __restrict__ out) {
    const int row = blockIdx.x * 8 + (threadIdx.x >> 5);   // row = b*TT + t
    const int lane = threadIdx.x & 31;
    float4 yv = ((const float4*)(g_y1 + (size_t)row * HH))[lane];
    float4 wv = ((const float4*)fc_w)[lane];
    float p = fmaxf(yv.x, 0.f) * wv.x + fmaxf(yv.y, 0.f) * wv.y
            + fmaxf(yv.z, 0.f) * wv.z + fmaxf(yv.w, 0.f) * wv.w;
    p += __shfl_xor_sync(0xffffffffu, p, 16);
    p += __shfl_xor_sync(0xffffffffu, p, 8);
    p += __shfl_xor_sync(0xffffffffu, p, 4);
    p += __shfl_xor_sync(0xffffffffu, p, 2);
    p += __shfl_xor_sync(0xffffffffu, p, 1);
    if (lane == 0) out[row] = p + fc_b[0];
}

extern "C" void kernel_launch(void* const* d_in, const int* in_sizes, int n_in,
                              void* d_out, int out_size) {
    const float* data   = (const float*)d_in[0];
    const float* hidden = (const float*)d_in[1];
    const float* w_ih0  = (const float*)d_in[2];
    const float* w_hh0  = (const float*)d_in[3];
    const float* b_ih0  = (const float*)d_in[4];
    const float* b_hh0  = (const float*)d_in[5];
    const float* w_ih1  = (const float*)d_in[6];
    const float* w_hh1  = (const float*)d_in[7];
    const float* b_ih1  = (const float*)d_in[8];
    const float* b_hh1  = (const float*)d_in[9];
    const float* fc_w   = (const float*)d_in[10];
    const float* fc_b   = (const float*)d_in[11];

    float* out = (float*)d_out;
    float* hT  = out + (size_t)BB * TT;   // [2,B,H] final hidden

    k_main<<<2 * NPAIR + NWORK, 384>>>(data, hidden, w_ih0, w_hh0, b_ih0, b_hh0,
                                       w_ih1, w_hh1, b_ih1, b_hh1, hT);
    k_fc<<<BB * TT / 8, 256>>>(fc_w, fc_b, out);
}